// round 8
// baseline (speedup 1.0000x reference)
#include <cuda_runtime.h>
#include <cuda_bf16.h>
#include <math.h>
#include <stdint.h>

// Problem constants
#define BB 2
#define SS 2048
#define DM 2048
#define HH 16
#define DH 128
#define NBH (BB*HH)
#define MROWS (BB*SS)        // 4096

// ---------------- scratch ------------------------------------------------------
__device__ __nv_bfloat16 g_xh[MROWS * DM], g_xl[MROWS * DM];
__device__ __nv_bfloat16 g_wh[4 * DM * DM], g_wl[4 * DM * DM];   // wq,wk,wv,wo
__device__ float         g_q [MROWS * DM];                        // fp32 pre-norm
__device__ float         g_k [MROWS * DM];
__device__ __nv_bfloat16 g_qh[MROWS * DM], g_ql[MROWS * DM];      // post rms+rope
__device__ __nv_bfloat16 g_kh[MROWS * DM], g_kl[MROWS * DM];
__device__ __nv_bfloat16 g_vth[(size_t)BB * HH * DH * SS];        // V^T (B,H,DH,S)
__device__ __nv_bfloat16 g_vtl[(size_t)BB * HH * DH * SS];
__device__ __nv_bfloat16 g_aoh[MROWS * DM], g_aol[MROWS * DM];

// ---------------- bf16 split helpers -------------------------------------------
__device__ __forceinline__ void split2(float a, float b, uint32_t& hi, uint32_t& lo) {
    __nv_bfloat16 ha = __float2bfloat16_rn(a);
    __nv_bfloat16 hb = __float2bfloat16_rn(b);
    __nv_bfloat16 la = __float2bfloat16_rn(a - __bfloat162float(ha));
    __nv_bfloat16 lb = __float2bfloat16_rn(b - __bfloat162float(hb));
    __nv_bfloat162 h2 = __halves2bfloat162(ha, hb);
    __nv_bfloat162 l2 = __halves2bfloat162(la, lb);
    hi = *reinterpret_cast<uint32_t*>(&h2);
    lo = *reinterpret_cast<uint32_t*>(&l2);
}
__device__ __forceinline__ void split1(float a, __nv_bfloat16& h, __nv_bfloat16& l) {
    h = __float2bfloat16_rn(a);
    l = __float2bfloat16_rn(a - __bfloat162float(h));
}

__device__ __forceinline__ void mma_bf16(float c[4],
    uint32_t a0, uint32_t a1, uint32_t a2, uint32_t a3,
    uint32_t b0, uint32_t b1)
{
    asm volatile(
        "mma.sync.aligned.m16n8k16.row.col.f32.bf16.bf16.f32 "
        "{%0,%1,%2,%3},{%4,%5,%6,%7},{%8,%9},{%0,%1,%2,%3};"
        : "+f"(c[0]), "+f"(c[1]), "+f"(c[2]), "+f"(c[3])
        : "r"(a0), "r"(a1), "r"(a2), "r"(a3), "r"(b0), "r"(b1));
}

// ---------------- one-time fp32 -> bf16 hi/lo split ----------------------------
__global__ void __launch_bounds__(256) split_kernel(
    const float* __restrict__ in, __nv_bfloat16* __restrict__ hi,
    __nv_bfloat16* __restrict__ lo, int n4)
{
    int i = blockIdx.x * 256 + threadIdx.x;
    if (i >= n4) return;
    float4 v = reinterpret_cast<const float4*>(in)[i];
    uint32_t h0, l0, h1, l1;
    split2(v.x, v.y, h0, l0);
    split2(v.z, v.w, h1, l1);
    reinterpret_cast<uint2*>(hi)[i] = make_uint2(h0, h1);
    reinterpret_cast<uint2*>(lo)[i] = make_uint2(l0, l1);
}

// ---------------- bf16 hi/lo NT GEMM: C = A @ B^T ------------------------------
// A,B given as hi/lo bf16 [*,K] row-major. 3-term compensated product.
// Tiles 128x128x32; 256 threads = 8 warps (2m x 4n).
// TV=true: epilogue writes transposed-V bf16 hi/lo (vt[b,h,d,s]).
#define TBM 128
#define TBN 128
#define TBK 32
#define SAS 40   // smem row stride in bf16 (32 + 8 pad); 80B, 16B-aligned

template <bool TV>
__global__ void __launch_bounds__(256) gemm_bf16(
    const __nv_bfloat16* __restrict__ Ah, const __nv_bfloat16* __restrict__ Al,
    const __nv_bfloat16* __restrict__ Bh, const __nv_bfloat16* __restrict__ Bl,
    float* __restrict__ C, __nv_bfloat16* __restrict__ Ch, __nv_bfloat16* __restrict__ Cl,
    int K, int lda, int ldb, int ldc)
{
    __shared__ __nv_bfloat16 sAh[TBM * SAS];
    __shared__ __nv_bfloat16 sAl[TBM * SAS];
    __shared__ __nv_bfloat16 sBh[TBN * SAS];
    __shared__ __nv_bfloat16 sBl[TBN * SAS];

    const int tid  = threadIdx.x;
    const int lane = tid & 31;
    const int wid  = tid >> 5;
    const int wm   = wid & 1;
    const int wn   = wid >> 1;
    const int row0 = blockIdx.y * TBM;
    const int col0 = blockIdx.x * TBN;

    // staging: row = (tid>>2) + 64*rr (0..127), c = (tid&3)*8 (0..24), uint4 = 8 bf16
    const int sr = tid >> 2;
    const int sc = (tid & 3) * 8;

    uint4 rah[2], ral[2], rbh[2], rbl[2];

    auto load_tile = [&](int k0) {
        #pragma unroll
        for (int rr = 0; rr < 2; rr++) {
            const size_t aoff = (size_t)(row0 + sr + 64 * rr) * lda + k0 + sc;
            const size_t boff = (size_t)(col0 + sr + 64 * rr) * ldb + k0 + sc;
            rah[rr] = *reinterpret_cast<const uint4*>(&Ah[aoff]);
            ral[rr] = *reinterpret_cast<const uint4*>(&Al[aoff]);
            rbh[rr] = *reinterpret_cast<const uint4*>(&Bh[boff]);
            rbl[rr] = *reinterpret_cast<const uint4*>(&Bl[boff]);
        }
    };

    auto store_tile = [&]() {
        #pragma unroll
        for (int rr = 0; rr < 2; rr++) {
            const int off = (sr + 64 * rr) * SAS + sc;
            *reinterpret_cast<uint4*>(&sAh[off]) = rah[rr];
            *reinterpret_cast<uint4*>(&sAl[off]) = ral[rr];
            *reinterpret_cast<uint4*>(&sBh[off]) = rbh[rr];
            *reinterpret_cast<uint4*>(&sBl[off]) = rbl[rr];
        }
    };

    float acc[4][4][4] = {};

    load_tile(0);
    store_tile();
    __syncthreads();

    for (int k0 = 0; k0 < K; k0 += TBK) {
        const bool more = (k0 + TBK) < K;
        if (more) load_tile(k0 + TBK);

        #pragma unroll
        for (int kk = 0; kk < 2; kk++) {
            const int kb = kk * 16 + (lane & 3) * 2;
            uint32_t ah[4][4], al[4][4];
            #pragma unroll
            for (int i = 0; i < 4; i++) {
                const int m = wm * 64 + i * 16 + (lane >> 2);
                ah[i][0] = *reinterpret_cast<const uint32_t*>(&sAh[m * SAS + kb]);
                ah[i][1] = *reinterpret_cast<const uint32_t*>(&sAh[(m + 8) * SAS + kb]);
                ah[i][2] = *reinterpret_cast<const uint32_t*>(&sAh[m * SAS + kb + 8]);
                ah[i][3] = *reinterpret_cast<const uint32_t*>(&sAh[(m + 8) * SAS + kb + 8]);
                al[i][0] = *reinterpret_cast<const uint32_t*>(&sAl[m * SAS + kb]);
                al[i][1] = *reinterpret_cast<const uint32_t*>(&sAl[(m + 8) * SAS + kb]);
                al[i][2] = *reinterpret_cast<const uint32_t*>(&sAl[m * SAS + kb + 8]);
                al[i][3] = *reinterpret_cast<const uint32_t*>(&sAl[(m + 8) * SAS + kb + 8]);
            }
            uint32_t bh[4][2], bl[4][2];
            #pragma unroll
            for (int j = 0; j < 4; j++) {
                const int n = wn * 32 + j * 8 + (lane >> 2);
                bh[j][0] = *reinterpret_cast<const uint32_t*>(&sBh[n * SAS + kb]);
                bh[j][1] = *reinterpret_cast<const uint32_t*>(&sBh[n * SAS + kb + 8]);
                bl[j][0] = *reinterpret_cast<const uint32_t*>(&sBl[n * SAS + kb]);
                bl[j][1] = *reinterpret_cast<const uint32_t*>(&sBl[n * SAS + kb + 8]);
            }
            #pragma unroll
            for (int i = 0; i < 4; i++)
                #pragma unroll
                for (int j = 0; j < 4; j++) {
                    mma_bf16(acc[i][j], ah[i][0], ah[i][1], ah[i][2], ah[i][3],
                             bh[j][0], bh[j][1]);
                    mma_bf16(acc[i][j], ah[i][0], ah[i][1], ah[i][2], ah[i][3],
                             bl[j][0], bl[j][1]);
                    mma_bf16(acc[i][j], al[i][0], al[i][1], al[i][2], al[i][3],
                             bh[j][0], bh[j][1]);
                }
        }
        __syncthreads();
        if (more) {
            store_tile();
            __syncthreads();
        }
    }

    if (TV) {
        // transposed V, bf16 hi/lo: vt[b, h=blockIdx.x, d, s]
        const int b = row0 / SS;
        const size_t base = ((size_t)(b * HH + blockIdx.x) * DH) * SS;
        #pragma unroll
        for (int i = 0; i < 4; i++) {
            const int s = (row0 - b * SS) + wm * 64 + i * 16 + (lane >> 2);
            #pragma unroll
            for (int j = 0; j < 4; j++) {
                const int d = wn * 32 + j * 8 + 2 * (lane & 3);
                __nv_bfloat16 h, l;
                split1(acc[i][j][0], h, l);
                Ch[base + (size_t)d * SS + s] = h;       Cl[base + (size_t)d * SS + s] = l;
                split1(acc[i][j][1], h, l);
                Ch[base + (size_t)(d+1) * SS + s] = h;   Cl[base + (size_t)(d+1) * SS + s] = l;
                split1(acc[i][j][2], h, l);
                Ch[base + (size_t)d * SS + s + 8] = h;   Cl[base + (size_t)d * SS + s + 8] = l;
                split1(acc[i][j][3], h, l);
                Ch[base + (size_t)(d+1) * SS + s + 8] = h; Cl[base + (size_t)(d+1) * SS + s + 8] = l;
            }
        }
    } else {
        #pragma unroll
        for (int i = 0; i < 4; i++) {
            const int r = row0 + wm * 64 + i * 16 + (lane >> 2);
            #pragma unroll
            for (int j = 0; j < 4; j++) {
                const int cc = col0 + wn * 32 + j * 8 + 2 * (lane & 3);
                float2 lo = make_float2(acc[i][j][0], acc[i][j][1]);
                float2 hi = make_float2(acc[i][j][2], acc[i][j][3]);
                *reinterpret_cast<float2*>(&C[(size_t)r * ldc + cc]) = lo;
                *reinterpret_cast<float2*>(&C[(size_t)(r + 8) * ldc + cc]) = hi;
            }
        }
    }
}

// ---------------- RMSNorm + RoPE: fp32 in -> bf16 hi/lo out --------------------
__global__ void __launch_bounds__(64) rmsnorm_rope_kernel(
    const float* __restrict__ t, const float* __restrict__ w,
    const float* __restrict__ freqs,
    __nv_bfloat16* __restrict__ oh, __nv_bfloat16* __restrict__ ol, float outscale)
{
    const int idx = blockIdx.x;              // b*S*H + s*H + h
    const int s = (idx / HH) % SS;
    const float* v = t + (size_t)idx * DH;
    const int i = threadIdx.x;               // 0..63

    float x0 = v[i];
    float x1 = v[i + 64];
    float ss = x0 * x0 + x1 * x1;
    #pragma unroll
    for (int o = 16; o > 0; o >>= 1) ss += __shfl_xor_sync(0xffffffffu, ss, o);
    __shared__ float sm[2];
    if ((i & 31) == 0) sm[i >> 5] = ss;
    __syncthreads();
    float total = sm[0] + sm[1];
    float r = rsqrtf(total * (1.0f / 128.0f) + 1e-6f);

    float n0 = x0 * r * w[i];
    float n1 = x1 * r * w[i + 64];

    const float* F = freqs + (size_t)s * 256 + i * 4;
    float y0 = (F[0] * n0 + F[1] * n1) * outscale;
    float y1 = (F[2] * n0 + F[3] * n1) * outscale;

    __nv_bfloat16 h, l;
    split1(y0, h, l);
    oh[(size_t)idx * DH + i] = h;       ol[(size_t)idx * DH + i] = l;
    split1(y1, h, l);
    oh[(size_t)idx * DH + i + 64] = h;  ol[(size_t)idx * DH + i + 64] = l;
}

// ---------------- Flash attention (bf16 hi/lo inputs) --------------------------
// grid (SS/128, NBH), 256 threads = 8 warps; warp w owns 16 q rows.
#define FKV 64
#define KST 136   // K smem row stride (bf16): 128 + 8 pad (272B, 16B-aligned)
#define VST 72    // V smem row stride (bf16): 64 + 8 pad (144B, 16B-aligned)

__global__ void __launch_bounds__(256) flash_kernel(
    const __nv_bfloat16* __restrict__ qh_g, const __nv_bfloat16* __restrict__ ql_g,
    const __nv_bfloat16* __restrict__ kh_g, const __nv_bfloat16* __restrict__ kl_g,
    const __nv_bfloat16* __restrict__ vth_g, const __nv_bfloat16* __restrict__ vtl_g,
    __nv_bfloat16* __restrict__ aoh, __nv_bfloat16* __restrict__ aol)
{
    extern __shared__ __nv_bfloat16 fsm[];
    __nv_bfloat16* Kh = fsm;
    __nv_bfloat16* Kl = Kh + FKV * KST;
    __nv_bfloat16* Vh = Kl + FKV * KST;
    __nv_bfloat16* Vl = Vh + DH * VST;

    const int tid  = threadIdx.x;
    const int lane = tid & 31;
    const int w    = tid >> 5;
    const int g    = lane >> 2;
    const int t    = lane & 3;
    const int bh   = blockIdx.y;
    const int b    = bh >> 4;
    const int h    = bh & 15;
    const int q0   = blockIdx.x * 128;

    const size_t qbase = ((size_t)(b * SS + q0)) * DM + h * DH;
    const size_t kbase = (size_t)b * SS * DM + h * DH;
    const size_t vbase = (size_t)bh * DH * SS;

    // ---- Q fragments in registers (hi/lo; scale pre-applied in rmsnorm) -------
    uint32_t qh[8][4], ql[8][4];
    {
        const size_t qw = qbase + (size_t)(w * 16) * DM;
        #pragma unroll
        for (int kc = 0; kc < 8; kc++) {
            #pragma unroll
            for (int e = 0; e < 4; e++) {
                const int r = g + ((e & 1) ? 8 : 0);
                const int c = kc * 16 + 2 * t + ((e & 2) ? 8 : 0);
                qh[kc][e] = *reinterpret_cast<const uint32_t*>(&qh_g[qw + (size_t)r * DM + c]);
                ql[kc][e] = *reinterpret_cast<const uint32_t*>(&ql_g[qw + (size_t)r * DM + c]);
            }
        }
    }

    float oacc[16][4] = {};
    float m0 = -INFINITY, m1 = -INFINITY, l0 = 0.0f, l1 = 0.0f;

    for (int kv0 = 0; kv0 < SS; kv0 += FKV) {
        __syncthreads();
        // ---- K tile: 64 rows x 128 bf16 (hi,lo) -------------------------------
        {
            const int row = tid >> 2;            // 0..63
            const int cb  = (tid & 3) * 32;
            const size_t src = kbase + (size_t)(kv0 + row) * DM;
            #pragma unroll
            for (int pc = 0; pc < 4; pc++) {
                const int c = cb + pc * 8;
                *reinterpret_cast<uint4*>(&Kh[row * KST + c]) =
                    *reinterpret_cast<const uint4*>(&kh_g[src + c]);
                *reinterpret_cast<uint4*>(&Kl[row * KST + c]) =
                    *reinterpret_cast<const uint4*>(&kl_g[src + c]);
            }
        }
        // ---- V tile: 128 dh rows x 64 kv (from vt) ----------------------------
        {
            const int row = tid >> 1;            // 0..127
            const int cb  = (tid & 1) * 32;
            const size_t src = vbase + (size_t)row * SS + kv0;
            #pragma unroll
            for (int pc = 0; pc < 4; pc++) {
                const int c = cb + pc * 8;
                *reinterpret_cast<uint4*>(&Vh[row * VST + c]) =
                    *reinterpret_cast<const uint4*>(&vth_g[src + c]);
                *reinterpret_cast<uint4*>(&Vl[row * VST + c]) =
                    *reinterpret_cast<const uint4*>(&vtl_g[src + c]);
            }
        }
        __syncthreads();

        // ---- S = Q @ K^T ------------------------------------------------------
        float sacc[8][4] = {};
        #pragma unroll
        for (int j = 0; j < 8; j++) {
            #pragma unroll
            for (int kc = 0; kc < 8; kc++) {
                const int off = (j * 8 + g) * KST + kc * 16 + 2 * t;
                uint32_t bh0 = *reinterpret_cast<const uint32_t*>(&Kh[off]);
                uint32_t bh1 = *reinterpret_cast<const uint32_t*>(&Kh[off + 8]);
                uint32_t bl0 = *reinterpret_cast<const uint32_t*>(&Kl[off]);
                uint32_t bl1 = *reinterpret_cast<const uint32_t*>(&Kl[off + 8]);
                mma_bf16(sacc[j], qh[kc][0], qh[kc][1], qh[kc][2], qh[kc][3], bh0, bh1);
                mma_bf16(sacc[j], qh[kc][0], qh[kc][1], qh[kc][2], qh[kc][3], bl0, bl1);
                mma_bf16(sacc[j], ql[kc][0], ql[kc][1], ql[kc][2], ql[kc][3], bh0, bh1);
            }
        }

        // ---- online softmax ---------------------------------------------------
        float mx0 = -INFINITY, mx1 = -INFINITY;
        #pragma unroll
        for (int j = 0; j < 8; j++) {
            mx0 = fmaxf(mx0, fmaxf(sacc[j][0], sacc[j][1]));
            mx1 = fmaxf(mx1, fmaxf(sacc[j][2], sacc[j][3]));
        }
        mx0 = fmaxf(mx0, __shfl_xor_sync(0xffffffffu, mx0, 1));
        mx0 = fmaxf(mx0, __shfl_xor_sync(0xffffffffu, mx0, 2));
        mx1 = fmaxf(mx1, __shfl_xor_sync(0xffffffffu, mx1, 1));
        mx1 = fmaxf(mx1, __shfl_xor_sync(0xffffffffu, mx1, 2));

        const float nm0 = fmaxf(m0, mx0), nm1 = fmaxf(m1, mx1);
        const float al0 = __expf(m0 - nm0), al1 = __expf(m1 - nm1);
        m0 = nm0; m1 = nm1;

        float s0 = 0.0f, s1 = 0.0f;
        #pragma unroll
        for (int j = 0; j < 8; j++) {
            sacc[j][0] = __expf(sacc[j][0] - nm0);
            sacc[j][1] = __expf(sacc[j][1] - nm0);
            sacc[j][2] = __expf(sacc[j][2] - nm1);
            sacc[j][3] = __expf(sacc[j][3] - nm1);
            s0 += sacc[j][0] + sacc[j][1];
            s1 += sacc[j][2] + sacc[j][3];
        }
        s0 += __shfl_xor_sync(0xffffffffu, s0, 1);
        s0 += __shfl_xor_sync(0xffffffffu, s0, 2);
        s1 += __shfl_xor_sync(0xffffffffu, s1, 1);
        s1 += __shfl_xor_sync(0xffffffffu, s1, 2);
        l0 = l0 * al0 + s0;
        l1 = l1 * al1 + s1;

        #pragma unroll
        for (int jn = 0; jn < 16; jn++) {
            oacc[jn][0] *= al0; oacc[jn][1] *= al0;
            oacc[jn][2] *= al1; oacc[jn][3] *= al1;
        }

        // ---- O += P @ V -------------------------------------------------------
        #pragma unroll
        for (int kc2 = 0; kc2 < 4; kc2++) {
            const int j0 = 2 * kc2, j1 = 2 * kc2 + 1;
            uint32_t pa0h, pa0l, pa1h, pa1l, pa2h, pa2l, pa3h, pa3l;
            split2(sacc[j0][0], sacc[j0][1], pa0h, pa0l);
            split2(sacc[j0][2], sacc[j0][3], pa1h, pa1l);
            split2(sacc[j1][0], sacc[j1][1], pa2h, pa2l);
            split2(sacc[j1][2], sacc[j1][3], pa3h, pa3l);
            #pragma unroll
            for (int jn = 0; jn < 16; jn++) {
                const int off = (jn * 8 + g) * VST + kc2 * 16 + 2 * t;
                uint32_t bh0 = *reinterpret_cast<const uint32_t*>(&Vh[off]);
                uint32_t bh1 = *reinterpret_cast<const uint32_t*>(&Vh[off + 8]);
                uint32_t bl0 = *reinterpret_cast<const uint32_t*>(&Vl[off]);
                uint32_t bl1 = *reinterpret_cast<const uint32_t*>(&Vl[off + 8]);
                mma_bf16(oacc[jn], pa0h, pa1h, pa2h, pa3h, bh0, bh1);
                mma_bf16(oacc[jn], pa0h, pa1h, pa2h, pa3h, bl0, bl1);
                mma_bf16(oacc[jn], pa0l, pa1l, pa2l, pa3l, bh0, bh1);
            }
        }
    }

    // ---- epilogue: O /= l, split to bf16 hi/lo --------------------------------
    const float inv0 = 1.0f / l0, inv1 = 1.0f / l1;
    #pragma unroll
    for (int jn = 0; jn < 16; jn++) {
        const int r = w * 16 + g;
        const int c = jn * 8 + 2 * t;
        uint32_t h01, l01, h23, l23;
        split2(oacc[jn][0] * inv0, oacc[jn][1] * inv0, h01, l01);
        split2(oacc[jn][2] * inv1, oacc[jn][3] * inv1, h23, l23);
        const size_t o0 = qbase + (size_t)r * DM + c;
        const size_t o1 = qbase + (size_t)(r + 8) * DM + c;
        *reinterpret_cast<uint32_t*>(&aoh[o0]) = h01;
        *reinterpret_cast<uint32_t*>(&aol[o0]) = l01;
        *reinterpret_cast<uint32_t*>(&aoh[o1]) = h23;
        *reinterpret_cast<uint32_t*>(&aol[o1]) = l23;
    }
}

// ---------------- launch -------------------------------------------------------
extern "C" void kernel_launch(void* const* d_in, const int* in_sizes, int n_in,
                              void* d_out, int out_size)
{
    const float* x     = (const float*)d_in[0];
    const float* rope  = (const float*)d_in[1];
    const float* wq    = (const float*)d_in[2];
    const float* wk    = (const float*)d_in[3];
    const float* wv    = (const float*)d_in[4];
    const float* wo    = (const float*)d_in[5];
    const float* qnw   = (const float*)d_in[6];
    const float* knw   = (const float*)d_in[7];
    float* out = (float*)d_out;

    __nv_bfloat16 *xh, *xl, *wh, *wl, *qh, *ql, *kh, *kl, *vth, *vtl, *aoh, *aol;
    float *q, *k;
    cudaGetSymbolAddress((void**)&xh,  g_xh);  cudaGetSymbolAddress((void**)&xl,  g_xl);
    cudaGetSymbolAddress((void**)&wh,  g_wh);  cudaGetSymbolAddress((void**)&wl,  g_wl);
    cudaGetSymbolAddress((void**)&q,   g_q);   cudaGetSymbolAddress((void**)&k,   g_k);
    cudaGetSymbolAddress((void**)&qh,  g_qh);  cudaGetSymbolAddress((void**)&ql,  g_ql);
    cudaGetSymbolAddress((void**)&kh,  g_kh);  cudaGetSymbolAddress((void**)&kl,  g_kl);
    cudaGetSymbolAddress((void**)&vth, g_vth); cudaGetSymbolAddress((void**)&vtl, g_vtl);
    cudaGetSymbolAddress((void**)&aoh, g_aoh); cudaGetSymbolAddress((void**)&aol, g_aol);

    cudaFuncSetAttribute(flash_kernel, cudaFuncAttributeMaxDynamicSharedMemorySize, 71680);
    static_assert((FKV * KST + DH * VST) * 4 == 71680, "smem size");

    const float scale = 0.08838834764831845f;  // 1/sqrt(128)
    const size_t WN = (size_t)DM * DM;

    // ---- one-time splits ------------------------------------------------------
    split_kernel<<<(MROWS * DM / 4 + 255) / 256, 256>>>(x, xh, xl, MROWS * DM / 4);
    split_kernel<<<(int)(WN / 4 + 255) / 256, 256>>>(wq, wh + 0 * WN, wl + 0 * WN, (int)(WN / 4));
    split_kernel<<<(int)(WN / 4 + 255) / 256, 256>>>(wk, wh + 1 * WN, wl + 1 * WN, (int)(WN / 4));
    split_kernel<<<(int)(WN / 4 + 255) / 256, 256>>>(wv, wh + 2 * WN, wl + 2 * WN, (int)(WN / 4));
    split_kernel<<<(int)(WN / 4 + 255) / 256, 256>>>(wo, wh + 3 * WN, wl + 3 * WN, (int)(WN / 4));

    // ---- QKV projections ------------------------------------------------------
    {
        dim3 grid(DM / TBN, MROWS / TBM, 1);
        gemm_bf16<false><<<grid, 256>>>(xh, xl, wh + 0 * WN, wl + 0 * WN,
                                        q, nullptr, nullptr, DM, DM, DM, DM);
        gemm_bf16<false><<<grid, 256>>>(xh, xl, wh + 1 * WN, wl + 1 * WN,
                                        k, nullptr, nullptr, DM, DM, DM, DM);
        gemm_bf16<true ><<<grid, 256>>>(xh, xl, wh + 2 * WN, wl + 2 * WN,
                                        nullptr, vth, vtl, DM, DM, DM, DM);
    }

    // ---- RMSNorm + RoPE -> bf16 hi/lo ----------------------------------------
    rmsnorm_rope_kernel<<<BB * SS * HH, 64>>>(q, qnw, rope, qh, ql, scale);
    rmsnorm_rope_kernel<<<BB * SS * HH, 64>>>(k, knw, rope, kh, kl, 1.0f);

    // ---- fused attention ------------------------------------------------------
    flash_kernel<<<dim3(SS / 128, NBH), 256, 71680>>>(qh, ql, kh, kl, vth, vtl, aoh, aol);

    // ---- output projection ----------------------------------------------------
    {
        dim3 grid(DM / TBN, MROWS / TBM, 1);
        gemm_bf16<false><<<grid, 256>>>(aoh, aol, wh + 3 * WN, wl + 3 * WN,
                                        out, nullptr, nullptr, DM, DM, DM, DM);
    }
}